// round 8
// baseline (speedup 1.0000x reference)
#include <cuda_runtime.h>
#include <cstdint>

// GRU B=64,T=4096,F=100,H=200,O=1. 32 clusters x 4 CTAs, 320 thr.
// Phase A: CTA-private gx = x·Wi -> scratch (verified R5 code).
// Phase B: recurrence. Warp w owns j in [5w,5w+5): 30 lanes = 3 gates x 2 batches
//   x 2 K-halves. Wh register-resident (104 regs/thread). K-halves combined by
//   shfl(15); gates combined by shfl(+5,+10). h exchanged via DSMEM pushes;
//   per-step rendezvous = SMEM mbarrier (count 4, cross-CTA release arrives).
// Phase C: y = h·Wo + bo GEMV (measured 47us).

#define Bq      64
#define Tq      4096
#define Fq      100
#define Hq      200
#define G3      600
#define BT      (Bq * Tq)
#define CLUSTER 4
#define BG      2
#define JPC     50
#define NTHR    320
#define TT      32
#define GRID    128

__device__ float g_gx[(size_t)GRID * Tq * BG * 160];   // CTA-private [t][b][160]
__device__ float g_h [(size_t)BT * Hq];                // [row=b*Tq+t][200]

__device__ __forceinline__ uint32_t smem_u32(const void* p) {
    return (uint32_t)__cvta_generic_to_shared(p);
}
__device__ __forceinline__ void st_cluster_f32(uint32_t laddr, uint32_t rr, float v) {
    uint32_t ra;
    asm volatile("mapa.shared::cluster.u32 %0, %1, %2;" : "=r"(ra) : "r"(laddr), "r"(rr));
    asm volatile("st.shared::cluster.f32 [%0], %1;" :: "r"(ra), "f"(v) : "memory");
}
__device__ __forceinline__ void mbar_init(uint32_t a, uint32_t cnt) {
    asm volatile("mbarrier.init.shared.b64 [%0], %1;" :: "r"(a), "r"(cnt) : "memory");
}
__device__ __forceinline__ void mbar_arrive_cluster(uint32_t local_a, uint32_t rr) {
    asm volatile(
        "{\n\t.reg .b32 ra;\n\t"
        "mapa.shared::cluster.u32 ra, %0, %1;\n\t"
        "mbarrier.arrive.release.cluster.shared::cluster.b64 _, [ra];\n\t}"
        :: "r"(local_a), "r"(rr) : "memory");
}
__device__ __forceinline__ void mbar_wait(uint32_t a, uint32_t parity) {
    asm volatile(
        "{\n\t.reg .pred P;\n\t"
        "WL_%=:\n\t"
        "mbarrier.try_wait.parity.acquire.cluster.shared::cta.b64 P, [%0], %1, 0x989680;\n\t"
        "@P bra.uni WD_%=;\n\t"
        "bra.uni WL_%=;\n\t"
        "WD_%=:\n\t}"
        :: "r"(a), "r"(parity) : "memory");
}
__device__ __forceinline__ void ffma2(unsigned long long& acc,
                                      unsigned long long a, unsigned long long b) {
    asm("fma.rn.f32x2 %0, %1, %2, %0;" : "+l"(acc) : "l"(a), "l"(b));
}
__device__ __forceinline__ float fold2(unsigned long long a, unsigned long long b) {
    unsigned long long s;
    asm("add.rn.f32x2 %0, %1, %2;" : "=l"(s) : "l"(a), "l"(b));
    return __uint_as_float((unsigned)s) + __uint_as_float((unsigned)(s >> 32));
}
__device__ __forceinline__ unsigned long long pack2(float a, float b) {
    return (unsigned long long)__float_as_uint(a) |
           ((unsigned long long)__float_as_uint(b) << 32);
}
__device__ __forceinline__ float sigf(float x) {
    return __fdividef(1.0f, 1.0f + __expf(-x));
}
__device__ __forceinline__ float tanh_fast(float x) {
    return 2.0f * sigf(2.0f * x) - 1.0f;
}

struct __align__(16) Smem {
    float h[2][BG][208];            // parity, batch (pads 200..207 zeroed)
    float xs[BG][TT][104];          // phase-A staging (pads 100..103 zeroed)
    unsigned long long mbar;
};

__global__ void __launch_bounds__(NTHR, 1)
gru_kernel(const float* __restrict__ x,  const float* __restrict__ Wi,
           const float* __restrict__ bi, const float* __restrict__ Wh,
           const float* __restrict__ bhn)
{
    extern __shared__ char smraw[];
    Smem* sm = reinterpret_cast<Smem*>(smraw);
    const int tid = threadIdx.x;
    uint32_t rank;
    asm("mov.u32 %0, %%cluster_ctarank;" : "=r"(rank));
    const int b0g = (blockIdx.x >> 2) * BG;
    float* gsl = &g_gx[(size_t)blockIdx.x * Tq * (BG * 160)];
    const uint32_t mba = smem_u32(&sm->mbar);

    // ---- one-time SMEM init ----
    for (int i = tid; i < 2 * BG * 208; i += NTHR)
        (&sm->h[0][0][0])[i] = 0.f;
    for (int i = tid; i < BG * TT * 4; i += NTHR) {
        int b2 = i / (TT * 4), rem = i - b2 * (TT * 4);
        sm->xs[b2][rem >> 2][100 + (rem & 3)] = 0.f;
    }
    if (tid == 0) mbar_init(mba, CLUSTER);
    __syncthreads();

    // ================= Phase A: gx = x · Wi (CTA-private slice) =================
    {
        const int c   = tid >> 1;        // 0..159 (c<150 real)
        const int b   = tid & 1;
        const bool act = (c < 150);
        int gcol = 0;
        if (act) { int g = c / JPC, j2 = c - g * JPC; gcol = g * Hq + (int)rank * JPC + j2; }

        ulonglong2 wr[26];               // k = 0..103 (100 real + 4 zero pad)
        #pragma unroll
        for (int q = 0; q < 26; ++q) {
            float v[4];
            #pragma unroll
            for (int r = 0; r < 4; ++r) {
                int k = q * 4 + r;
                v[r] = (act && k < Fq) ? Wi[(size_t)k * G3 + gcol] : 0.f;
            }
            wr[q].x = pack2(v[0], v[1]);
            wr[q].y = pack2(v[2], v[3]);
        }

        for (int t0 = 0; t0 < Tq; t0 += TT) {
            __syncthreads();
            for (int i = tid; i < BG * TT * Fq; i += NTHR) {
                int b2 = i / (TT * Fq), rem = i - b2 * (TT * Fq);
                int r = rem / Fq, f = rem - r * Fq;
                sm->xs[b2][r][f] =
                    x[(size_t)(b0g + b2) * (Tq * Fq) + (size_t)(t0 + r) * Fq + f];
            }
            __syncthreads();
            if (act) {
                for (int r = 0; r < TT; ++r) {
                    const ulonglong2* vp = reinterpret_cast<const ulonglong2*>(sm->xs[b][r]);
                    unsigned long long a0 = 0, a1 = 0;
                    #pragma unroll
                    for (int q = 0; q < 26; ++q) {
                        ulonglong2 v = vp[q];
                        ffma2(a0, wr[q].x, v.x);
                        ffma2(a1, wr[q].y, v.y);
                    }
                    gsl[(size_t)(t0 + r) * (BG * 160) + b * 160 + c] = fold2(a0, a1);
                }
            }
        }
    }
    __syncthreads();   // gsl writes visible CTA-wide

    // ================= Phase B: recurrence =================
    const int wid  = tid >> 5, lane = tid & 31;
    const bool act = (lane < 30);
    const int lr   = act ? (lane % 15) : 0;   // 0..14
    const int half = act ? (lane / 15) : 0;   // K-half
    const int gate = lr / 5;                  // 0=r 1=z 2=n
    const int j    = wid * 5 + (lr % 5);      // 0..49
    const int col  = gate * JPC + j;          // gx column 0..149
    const int gcol = gate * Hq + (int)rank * JPC + j;
    const int jg   = (int)rank * JPC + j;

    // register-resident Wh: column gcol, K-half slice (104 floats = 52 packed)
    unsigned long long wreg[52];
    #pragma unroll
    for (int i = 0; i < 52; ++i) {
        int k0 = half * 104 + 2 * i;
        float v0 = (act && k0     < Hq) ? Wh[(size_t)(k0    ) * G3 + gcol] : 0.f;
        float v1 = (act && k0 + 1 < Hq) ? Wh[(size_t)(k0 + 1) * G3 + gcol] : 0.f;
        wreg[i] = pack2(v0, v1);
    }

    // per-lane constants (holders = lanes 0..14)
    const bool holder = (lane < 15);
    const float bi_c  = act ? bi[gcol] : 0.f;
    const float bhn_c = act ? bhn[jg] : 0.f;
    const float* gxp  = gsl + col;             // + t*320 + b*160
    const size_t hb0  = ((size_t)(b0g + 0) * Tq) * Hq + jg;
    const size_t hb1  = ((size_t)(b0g + 1) * Tq) * Hq + jg;

    // 2-deep gx pipeline (holders)
    float g0b0 = 0.f, g0b1 = 0.f, g1b0 = 0.f, g1b1 = 0.f;
    if (holder) {
        g0b0 = gxp[0];   g0b1 = gxp[160];
        g1b0 = gxp[320]; g1b1 = gxp[480];
    }
    float hp0 = 0.f, hp1 = 0.f;   // owner-lane h state

    // all CTAs: SMEM (h zeros + mbar) initialized before any arrive
    asm volatile("barrier.cluster.arrive.aligned;" ::: "memory");
    asm volatile("barrier.cluster.wait.aligned;"   ::: "memory");
    if (tid == 0) {
        #pragma unroll
        for (uint32_t rr = 0; rr < CLUSTER; ++rr) mbar_arrive_cluster(mba, rr);
    }

    int ph = 0;
    for (int t = 0; t < Tq; ++t) {
        const int par = t & 1;

        mbar_wait(mba, ph);  ph ^= 1;          // h[par] complete in local SMEM

        // ---- dot: K-half, both batches (52 LDS.128 + 104 FFMA2) ----
        float d0, d1;
        {
            const ulonglong2* vb0 =
                reinterpret_cast<const ulonglong2*>(&sm->h[par][0][half * 104]);
            const ulonglong2* vb1 =
                reinterpret_cast<const ulonglong2*>(&sm->h[par][1][half * 104]);
            unsigned long long a0x = 0, a0y = 0, a1x = 0, a1y = 0;
            #pragma unroll
            for (int q = 0; q < 26; ++q) {
                ulonglong2 v0 = vb0[q], v1 = vb1[q];
                ffma2(a0x, wreg[2 * q], v0.x); ffma2(a0y, wreg[2 * q + 1], v0.y);
                ffma2(a1x, wreg[2 * q], v1.x); ffma2(a1y, wreg[2 * q + 1], v1.y);
            }
            d0 = fold2(a0x, a0y);
            d1 = fold2(a1x, a1y);
        }
        // combine K-halves: lanes 0..14 get lane+15's partial
        d0 += __shfl_down_sync(0xffffffffu, d0, 15);
        d1 += __shfl_down_sync(0xffffffffu, d1, 15);

        // ---- per-gate values (holders) ----
        float s0 = d0 + g0b0 + bi_c;
        float s1 = d1 + g0b1 + bi_c;
        float sg0 = sigf(s0), sg1 = sigf(s1);
        float v1b0 = (gate == 2) ? (d0 + bhn_c) : sg0;   // r/z: sigmoid; n: u = dot+bhn
        float v1b1 = (gate == 2) ? (d1 + bhn_c) : sg1;
        float v2b0 = g0b0 + bi_c;                        // n: g = gx+bi
        float v2b1 = g0b1 + bi_c;

        // gate combine via shfl (owner = lane<5, its own v1 = r)
        float z0 = __shfl_sync(0xffffffffu, v1b0, lane + 5);
        float z1 = __shfl_sync(0xffffffffu, v1b1, lane + 5);
        float u0 = __shfl_sync(0xffffffffu, v1b0, lane + 10);
        float u1 = __shfl_sync(0xffffffffu, v1b1, lane + 10);
        float w0 = __shfl_sync(0xffffffffu, v2b0, lane + 10);
        float w1 = __shfl_sync(0xffffffffu, v2b1, lane + 10);

        if (lane < 5) {
            float n0 = tanh_fast(w0 + v1b0 * u0);
            float n1 = tanh_fast(w1 + v1b1 * u1);
            float h0 = n0 + z0 * (hp0 - n0);
            float h1 = n1 + z1 * (hp1 - n1);
            hp0 = h0; hp1 = h1;
            uint32_t la0 = smem_u32(&sm->h[par ^ 1][0][jg]);
            uint32_t la1 = smem_u32(&sm->h[par ^ 1][1][jg]);
            #pragma unroll
            for (uint32_t rr = 0; rr < CLUSTER; ++rr) {
                st_cluster_f32(la0, rr, h0);
                st_cluster_f32(la1, rr, h1);
            }
            g_h[hb0 + (size_t)t * Hq] = h0;
            g_h[hb1 + (size_t)t * Hq] = h1;
        }
        __syncthreads();                        // all pushes issued, CTA-ordered
        if (tid == 0) {
            #pragma unroll
            for (uint32_t rr = 0; rr < CLUSTER; ++rr) mbar_arrive_cluster(mba, rr);
        }

        // shift gx pipeline; prefetch t+2
        g0b0 = g1b0; g0b1 = g1b1;
        if (holder && (t + 2 < Tq)) {
            const float* p = gxp + (size_t)(t + 2) * (BG * 160);
            g1b0 = p[0]; g1b1 = p[160];
        }
    }

    // no CTA may exit while peers' pushes to its SMEM are in flight
    asm volatile("barrier.cluster.arrive.aligned;" ::: "memory");
    asm volatile("barrier.cluster.wait.aligned;"   ::: "memory");
}

// ================= Phase C: y = h · Wo + bo =================
__global__ void __launch_bounds__(256)
y_kernel(const float* __restrict__ Wo, const float* __restrict__ bo,
         float* __restrict__ out)
{
    __shared__ float wos[Hq];
    const int tid = threadIdx.x;
    if (tid < Hq) wos[tid] = Wo[tid];
    __syncthreads();
    const float bo0 = bo[0];
    const int lane = tid & 31;
    const int gw   = (blockIdx.x * 256 + tid) >> 5;
    const int nw   = (gridDim.x * 256) >> 5;
    for (int row = gw; row < BT; row += nw) {
        const float* hr = g_h + (size_t)row * Hq;
        float s = 0.f;
        #pragma unroll
        for (int k = lane; k < Hq; k += 32) s = fmaf(hr[k], wos[k], s);
        #pragma unroll
        for (int m = 16; m > 0; m >>= 1) s += __shfl_xor_sync(0xffffffffu, s, m);
        if (lane == 0) out[row] = s + bo0;
    }
}

extern "C" void kernel_launch(void* const* d_in, const int* in_sizes, int n_in,
                              void* d_out, int out_size) {
    (void)in_sizes; (void)n_in; (void)out_size;
    const float* x   = (const float*)d_in[0];
    const float* Wi  = (const float*)d_in[1];
    const float* bi  = (const float*)d_in[2];
    const float* Wh  = (const float*)d_in[3];
    const float* bhn = (const float*)d_in[4];
    const float* Wo  = (const float*)d_in[5];
    const float* bo  = (const float*)d_in[6];
    float* out = (float*)d_out;

    cudaFuncSetAttribute(gru_kernel, cudaFuncAttributeMaxDynamicSharedMemorySize,
                         (int)sizeof(Smem));
    cudaLaunchConfig_t cfg = {};
    cfg.gridDim  = dim3(GRID, 1, 1);
    cfg.blockDim = dim3(NTHR, 1, 1);
    cfg.dynamicSmemBytes = sizeof(Smem);
    cfg.stream = 0;
    cudaLaunchAttribute attr[1];
    attr[0].id = cudaLaunchAttributeClusterDimension;
    attr[0].val.clusterDim.x = CLUSTER;
    attr[0].val.clusterDim.y = 1;
    attr[0].val.clusterDim.z = 1;
    cfg.attrs = attr;
    cfg.numAttrs = 1;
    cudaLaunchKernelEx(&cfg, gru_kernel, x, Wi, bi, Wh, bhn);

    y_kernel<<<592, 256>>>(Wo, bo, out);
}